// round 16
// baseline (speedup 1.0000x reference)
#include <cuda_runtime.h>
#include <stdint.h>

#define TPB 64

__constant__ uint32_t cK[64] = {
    0xd76aa478u,0xe8c7b756u,0x242070dbu,0xc1bdceeeu,
    0xf57c0fafu,0x4787c62au,0xa8304613u,0xfd469501u,
    0x698098d8u,0x8b44f7afu,0xffff5bb1u,0x895cd7beu,
    0x6b901122u,0xfd987193u,0xa679438eu,0x49b40821u,
    0xf61e2562u,0xc040b340u,0x265e5a51u,0xe9b6c7aau,
    0xd62f105du,0x02441453u,0xd8a1e681u,0xe7d3fbc8u,
    0x21e1cde6u,0xc33707d6u,0xf4d50d87u,0x455a14edu,
    0xa9e3e905u,0xfcefa3f8u,0x676f02d9u,0x8d2a4c8au,
    0xfffa3942u,0x8771f681u,0x6d9d6122u,0xfde5380cu,
    0xa4beea44u,0x4bdecfa9u,0xf6bb4b60u,0xbebfbc70u,
    0x289b7ec6u,0xeaa127fau,0xd4ef3085u,0x04881d05u,
    0xd9d4d039u,0xe6db99e5u,0x1fa27cf8u,0xc4ac5665u,
    0xf4292244u,0x432aff97u,0xab9423a7u,0xfc93a039u,
    0x655b59c3u,0x8f0ccc92u,0xffeff47du,0x85845dd1u,
    0x6fa87e4fu,0xfe2ce6e0u,0xa3014314u,0x4e0811a1u,
    0xf7537e82u,0xbd3af235u,0x2ad7d2bbu,0xeb86d391u };

__constant__ uint8_t cS[64] = {
    7,12,17,22, 7,12,17,22, 7,12,17,22, 7,12,17,22,
    5, 9,14,20, 5, 9,14,20, 5, 9,14,20, 5, 9,14,20,
    4,11,16,23, 4,11,16,23, 4,11,16,23, 4,11,16,23,
    6,10,15,21, 6,10,15,21, 6,10,15,21, 6,10,15,21 };

__constant__ uint8_t cG[64] = {
    0,1,2,3,4,5,6,7,8,9,10,11,12,13,14,15,
    1,6,11,0,5,10,15,4,9,14,3,8,13,2,7,12,
    5,8,11,14,1,4,7,10,13,0,3,6,9,12,15,2,
    0,7,14,5,12,3,10,1,8,15,6,13,4,11,2,9 };

// ---- f32 soft ops, exact IEEE-RN, reference association --------------------
__device__ __forceinline__ float fxor(float a, float b) {
    return __fsub_rn(__fadd_rn(a, b), __fmul_rn(__fmul_rn(2.0f, a), b));
}
__device__ __forceinline__ float fand(float a, float b) { return __fmul_rn(a, b); }
__device__ __forceinline__ float forr(float a, float b) {
    return __fsub_rn(__fadd_rn(a, b), __fmul_rn(a, b));
}
__device__ __forceinline__ float fnot(float a) { return __fsub_rn(1.0f, a); }

__device__ __forceinline__ float decst(int st) {
    if (!(st & 1)) return 0.0f;
    return (st & 2) ? __uint_as_float(0x3F7FFFFFu) : 1.0f;
}
__device__ __forceinline__ float fphase(int ph, float b, float c, float d) {
    if (ph == 0) return forr(fand(b, c), fand(fnot(b), d));
    if (ph == 1) return forr(fand(d, b), fand(fnot(d), c));
    if (ph == 2) return fxor(fxor(b, c), d);
    return fxor(c, forr(b, fnot(d)));
}
// deficit predicate: soft_add32 result bit is (1-2^-24) iff hard=1 AND this
__device__ __forceinline__ uint32_t pbit(float x, float y) {
    float px = __fmul_rn(fxor(x, y), 0.5f);
    float r  = __fsub_rn(__fadd_rn(1.0f, px), px);
    return (__float_as_uint(r) != 0x3F800000u) ? 1u : 0u;
}

// ---- RN to 53-bit significand (RNE) of u64, x < 2^57; branchless magic -----
__device__ __forceinline__ uint64_t rn53(uint64_t x) {
    if (x < (1ull << 53)) return x;
    int sh = 11 - __clz((uint32_t)(x >> 32));
    uint64_t m = 1ull << sh;
    uint64_t y = x + (m >> 1) - 1ull + ((x >> sh) & 1ull);
    return y & (0ull - m);
}
// sequential f64 value of a T-valued word, 2^-24 units (R3-validated order)
__device__ __forceinline__ uint64_t tvalm(uint32_t H, uint32_t P) {
    uint64_t E = (((uint64_t)(H & 0x1FFFFFFFu)) << 24) - (uint64_t)(P & 0x1FFFFFFFu);
#pragma unroll
    for (int i = 29; i < 32; i++) {
        uint64_t t = (((uint64_t)((H >> i) & 1u)) << (24 + i)) -
                     (((uint64_t)((P >> i) & 1u)) << i);
        E = rn53(E + t);
    }
    return E;
}
// floor(sv / 2^24) mod 2^32 for nonneg f64 sv < 2^57 — off the CVT pipe
__device__ __forceinline__ uint32_t h32of(double sv) {
    uint64_t b = (uint64_t)__double_as_longlong(sv);
    uint32_t e = (uint32_t)(b >> 52);
    uint64_t m = (b & 0x000FFFFFFFFFFFFFull) | 0x0010000000000000ull;
    uint32_t t = 1099u - e;
    return (t >= 64u) ? 0u : (uint32_t)(m >> t);
}
__device__ __forceinline__ uint32_t spread4(uint32_t x, int q) {
    return (((x >> (4 * q)) & 0xFu) * 0x00204081u) & 0x01010101u;
}
__device__ __forceinline__ uint32_t gatherk(const uint32_t* Y, int k) {
    uint32_t m = 0;
#pragma unroll
    for (int q = 0; q < 8; q++) {
        uint32_t t = (Y[q] >> k) & 0x01010101u;
        m |= (((t * 0x01020408u) >> 24) & 0xFu) << (4 * q);
    }
    return m;
}

// T (+) T soft_add32 on masks (alias-safe)
__device__ __forceinline__ void tadd(uint32_t Hx, uint32_t Px, uint64_t vx,
                                     uint32_t Hy, uint32_t Py, uint64_t vy,
                                     uint32_t& Ho, uint32_t& Po, uint64_t& vo) {
    uint32_t ho = (uint32_t)(rn53(vx + vy) >> 24);
    uint32_t po = ho & (Hx & Hy & (Px | Py));
    uint64_t vv = tvalm(ho, po);
    Ho = ho; Po = po; vo = vv;
}

#define C2P55 36028797018963968.0   // 2^55

// ---- one MD5 compress over byte-packed T-state -------------------------------
template<int BLK2>
__device__ void compress_fn(
    uint32_t& Ha, uint32_t& Pa, uint64_t& va,
    uint32_t& Hb, uint32_t& Pb, uint64_t& vb,
    uint32_t& Hc, uint32_t& Pc, uint64_t& vc,
    uint32_t& Hd, uint32_t& Pd, uint64_t& vd,
    const uint64_t* sTbl,
    const uint64_t* wvu, const uint32_t* m0, const uint32_t* x1, const uint32_t* x2)
{
    // byte-packed state: byte j = b2 | c2<<2 | d2<<4 | a2<<6
    uint32_t Y[8];
#pragma unroll
    for (int q = 0; q < 8; q++) {
        Y[q] = spread4(Hb,q)        | (spread4(Pb,q) << 1)
             | (spread4(Hc,q) << 2) | (spread4(Pc,q) << 3)
             | (spread4(Hd,q) << 4) | (spread4(Pd,q) << 5)
             | (spread4(Ha,q) << 6) | (spread4(Pa,q) << 7);
    }
    uint32_t HB = Hb, PB = Pb;
    double vaf = __ull2double_rn(va), vbf = __ull2double_rn(vb);
    double vcf = __ull2double_rn(vc), vdf = __ull2double_rn(vd);

#pragma unroll 2
    for (int i = 0; i < 64; i++) {
        const uint64_t* ft = sTbl + ((i >> 4) << 8);
        // f-sum: faithful f64 Horner chain, one q-group load-ahead (software
        // pipeline pulls LDS latency off the DFMA chain)
        double r = 0.0;
        uint32_t pred1 = 0;
        uint64_t e0, e1, e2, e3;
        {
            uint32_t yq = Y[0];
            e0 = ft[__byte_perm(yq, 0, 0x4440)];
            e1 = ft[__byte_perm(yq, 0, 0x4441)];
            e2 = ft[__byte_perm(yq, 0, 0x4442)];
            e3 = ft[__byte_perm(yq, 0, 0x4443)];
        }
#pragma unroll
        for (int q = 0; q < 8; q++) {
            uint64_t c0 = e0, c1 = e1, c2 = e2, c3 = e3;
            if (q < 7) {
                uint32_t yn = Y[q + 1];
                e0 = ft[__byte_perm(yn, 0, 0x4440)];
                e1 = ft[__byte_perm(yn, 0, 0x4441)];
                e2 = ft[__byte_perm(yn, 0, 0x4442)];
                e3 = ft[__byte_perm(yn, 0, 0x4443)];
            }
            pred1 |= ((uint32_t)c0 & 1u) << (4*q+0);
            r = __fma_rn(r, 0.5, __longlong_as_double((long long)(c0 & ~1ull)));
            pred1 |= ((uint32_t)c1 & 1u) << (4*q+1);
            r = __fma_rn(r, 0.5, __longlong_as_double((long long)(c1 & ~1ull)));
            pred1 |= ((uint32_t)c2 & 1u) << (4*q+2);
            r = __fma_rn(r, 0.5, __longlong_as_double((long long)(c2 & ~1ull)));
            pred1 |= ((uint32_t)c3 & 1u) << (4*q+3);
            r = __fma_rn(r, 0.5, __longlong_as_double((long long)(c3 & ~1ull)));
        }
        // add1: f-sum + a  (exact product 2^55, one RN == reference)
        double sv = __fma_rn(r, C2P55, vaf);
        uint32_t H1 = h32of(sv);
        uint32_t P1 = H1 & pred1;
        uint64_t v1 = tvalm(H1, P1);
        // add2: + K[i]
        uint32_t Km = cK[i];
        uint32_t H2 = (uint32_t)(rn53(v1 + (((uint64_t)Km) << 24)) >> 24);
        uint32_t P2 = H2 & (Km & P1);
        uint64_t v2 = tvalm(H2, P2);
        // add3: + word[g]
        int g = cG[i];
        uint32_t H3, P3;
        if (BLK2) {
            uint64_t pw  = (g == 0) ? (0x80ull << 24) : ((g == 14) ? (0x200ull << 24) : 0ull);
            uint32_t pwm = (g == 0) ? 0x80u : ((g == 14) ? 0x200u : 0u);
            H3 = (uint32_t)(rn53(v2 + pw) >> 24);
            P3 = H3 & (P2 & pwm);
        } else {
            H3 = (uint32_t)(rn53(v2 + wvu[g]) >> 24);
            uint32_t pr = m0[g] ^ (H2 & x1[g]) ^ (P2 & x2[g]);
            P3 = H3 & pr;
        }
        // rotate, then b = soft_add32(b, rot)
        int sh = cS[i];
        uint32_t H3r = __funnelshift_l(H3, H3, sh);
        uint32_t P3r = __funnelshift_l(P3, P3, sh);
        uint64_t v3 = tvalm(H3r, P3r);
        uint32_t H4 = (uint32_t)(rn53(vb + v3) >> 24);
        uint32_t P4 = H4 & (HB & H3r & (PB | P3r));
        uint64_t v4 = tvalm(H4, P4);
        double v4f = __ull2double_rn(v4);   // exact; consumed next round
        // shift state bytes b->c->d->a; insert new b
#pragma unroll
        for (int q = 0; q < 8; q++) {
            uint32_t bb = spread4(H4, q) | (spread4(P4, q) << 1);
            Y[q] = ((Y[q] & 0x3F3F3F3Fu) << 2) | bb;
        }
        va = vd;  vd = vc;  vc = vb;  vb = v4;
        vaf = vdf; vdf = vcf; vcf = vbf; vbf = v4f;
        HB = H4; PB = P4;
    }
    // recover final masks from Y
    Hb = HB;           Pb = PB;
    Hc = gatherk(Y,2); Pc = gatherk(Y,3);
    Hd = gatherk(Y,4); Pd = gatherk(Y,5);
    Ha = gatherk(Y,6); Pa = gatherk(Y,7);
}

__global__ void __launch_bounds__(TPB, 12)
softmd5_kernel(const float* __restrict__ in, float* __restrict__ out, int B)
{
    // 4 phases x 256 entries: f64(f) bits with pred(code,ast) in mantissa bit0
    __shared__ uint64_t sTbl[4 * 256];

    int t = threadIdx.x;
    const float ONEME = __uint_as_float(0x3F7FFFFFu);
    for (int k = t; k < 1024; k += TPB) {
        int ph = k >> 8, Bc = k & 255;
        float b = decst(Bc & 3), c = decst((Bc >> 2) & 3), d = decst((Bc >> 4) & 3);
        float a = decst((Bc >> 6) & 3);
        float f = fphase(ph, b, c, d);
        uint64_t bits = (uint64_t)__double_as_longlong((double)f); // low mant bits 0
        sTbl[k] = (bits & ~1ull) | (uint64_t)pbit(f, a);
    }
    __syncthreads();

    int row = blockIdx.x * TPB + t;
    if (row >= B) return;

    const float4* rp = reinterpret_cast<const float4*>(in + (size_t)row * 512);

    // word values: f64 Horner chain (reference-exact), converted to u64 units
    uint64_t wvu[16];
    uint32_t m0[16], x1[16], x2[16];
#pragma unroll 1
    for (int g = 0; g < 16; g++) {
        double hr = 0.0;
        uint32_t a0 = 0, a1 = 0, a2 = 0;
        for (int q = 0; q < 8; q++) {
            float4 w4 = rp[g * 8 + q];
            float w[4] = { w4.x, w4.y, w4.z, w4.w };
#pragma unroll
            for (int u = 0; u < 4; u++) {
                int j = q * 4 + u;
                hr = __fma_rn(hr, 0.5, (double)w[u]);
                a0 |= pbit(0.0f,  w[u]) << j;
                a1 |= pbit(1.0f,  w[u]) << j;
                a2 |= pbit(ONEME, w[u]) << j;
            }
        }
        wvu[g] = __double2ull_rz(__dmul_rn(hr, C2P55));
        m0[g] = a0; x1[g] = a0 ^ a1; x2[g] = a1 ^ a2;
    }

    // H-state (T-masks + cached value, 2^-24 units u64)
    uint32_t HA = 0x67452301u, PA = 0, HB = 0xefcdab89u, PB = 0;
    uint32_t HC = 0x98badcfeu, PC = 0, HD = 0x10325476u, PD = 0;
    uint64_t VA = ((uint64_t)HA) << 24, VB = ((uint64_t)HB) << 24;
    uint64_t VC = ((uint64_t)HC) << 24, VD = ((uint64_t)HD) << 24;

    // ---- block 1 ----
    {
        uint32_t ha=HA,pa=PA,hb=HB,pb=PB,hc=HC,pc=PC,hd=HD,pd=PD;
        uint64_t va=VA,vb=VB,vc=VC,vd=VD;
        compress_fn<0>(ha,pa,va, hb,pb,vb, hc,pc,vc, hd,pd,vd,
                       sTbl, wvu, m0, x1, x2);
        tadd(HA,PA,VA, ha,pa,va, HA,PA,VA);
        tadd(HB,PB,VB, hb,pb,vb, HB,PB,VB);
        tadd(HC,PC,VC, hc,pc,vc, HC,PC,VC);
        tadd(HD,PD,VD, hd,pd,vd, HD,PD,VD);
    }
    // ---- block 2 (constant padding) ----
    {
        uint32_t ha=HA,pa=PA,hb=HB,pb=PB,hc=HC,pc=PC,hd=HD,pd=PD;
        uint64_t va=VA,vb=VB,vc=VC,vd=VD;
        compress_fn<1>(ha,pa,va, hb,pb,vb, hc,pc,vc, hd,pd,vd,
                       sTbl, wvu, m0, x1, x2);
        tadd(HA,PA,VA, ha,pa,va, HA,PA,VA);
        tadd(HB,PB,VB, hb,pb,vb, HB,PB,VB);
        tadd(HC,PC,VC, hc,pc,vc, HC,PC,VC);
        tadd(HD,PD,VD, hd,pd,vd, HD,PD,VD);
    }

    // ---- emit 128 float bits ----
    float4* op = reinterpret_cast<float4*>(out + (size_t)row * 128);
    uint32_t Hs[4] = { HA, HB, HC, HD }, Ps[4] = { PA, PB, PC, PD };
#pragma unroll
    for (int w = 0; w < 4; w++) {
        uint32_t Hm = Hs[w], Pm = Ps[w];
#pragma unroll
        for (int j = 0; j < 32; j += 4) {
            float4 f4;
            f4.x = __uint_as_float(((Hm>>(j+0))&1u) ? (((Pm>>(j+0))&1u)?0x3F7FFFFFu:0x3F800000u) : 0u);
            f4.y = __uint_as_float(((Hm>>(j+1))&1u) ? (((Pm>>(j+1))&1u)?0x3F7FFFFFu:0x3F800000u) : 0u);
            f4.z = __uint_as_float(((Hm>>(j+2))&1u) ? (((Pm>>(j+2))&1u)?0x3F7FFFFFu:0x3F800000u) : 0u);
            f4.w = __uint_as_float(((Hm>>(j+3))&1u) ? (((Pm>>(j+3))&1u)?0x3F7FFFFFu:0x3F800000u) : 0u);
            op[w*8 + (j>>2)] = f4;
        }
    }
}

extern "C" void kernel_launch(void* const* d_in, const int* in_sizes, int n_in,
                              void* d_out, int out_size)
{
    const float* in = (const float*)d_in[0];
    float* out = (float*)d_out;
    int B = in_sizes[0] / 512;            // 131072 rows
    int blocks = (B + TPB - 1) / TPB;
    softmd5_kernel<<<blocks, TPB>>>(in, out, B);
}

// round 17
// speedup vs baseline: 1.1159x; 1.1159x over previous
#include <cuda_runtime.h>
#include <stdint.h>

#define TPB 64

__constant__ uint32_t cK[64] = {
    0xd76aa478u,0xe8c7b756u,0x242070dbu,0xc1bdceeeu,
    0xf57c0fafu,0x4787c62au,0xa8304613u,0xfd469501u,
    0x698098d8u,0x8b44f7afu,0xffff5bb1u,0x895cd7beu,
    0x6b901122u,0xfd987193u,0xa679438eu,0x49b40821u,
    0xf61e2562u,0xc040b340u,0x265e5a51u,0xe9b6c7aau,
    0xd62f105du,0x02441453u,0xd8a1e681u,0xe7d3fbc8u,
    0x21e1cde6u,0xc33707d6u,0xf4d50d87u,0x455a14edu,
    0xa9e3e905u,0xfcefa3f8u,0x676f02d9u,0x8d2a4c8au,
    0xfffa3942u,0x8771f681u,0x6d9d6122u,0xfde5380cu,
    0xa4beea44u,0x4bdecfa9u,0xf6bb4b60u,0xbebfbc70u,
    0x289b7ec6u,0xeaa127fau,0xd4ef3085u,0x04881d05u,
    0xd9d4d039u,0xe6db99e5u,0x1fa27cf8u,0xc4ac5665u,
    0xf4292244u,0x432aff97u,0xab9423a7u,0xfc93a039u,
    0x655b59c3u,0x8f0ccc92u,0xffeff47du,0x85845dd1u,
    0x6fa87e4fu,0xfe2ce6e0u,0xa3014314u,0x4e0811a1u,
    0xf7537e82u,0xbd3af235u,0x2ad7d2bbu,0xeb86d391u };

__constant__ uint8_t cS[64] = {
    7,12,17,22, 7,12,17,22, 7,12,17,22, 7,12,17,22,
    5, 9,14,20, 5, 9,14,20, 5, 9,14,20, 5, 9,14,20,
    4,11,16,23, 4,11,16,23, 4,11,16,23, 4,11,16,23,
    6,10,15,21, 6,10,15,21, 6,10,15,21, 6,10,15,21 };

__constant__ uint8_t cG[64] = {
    0,1,2,3,4,5,6,7,8,9,10,11,12,13,14,15,
    1,6,11,0,5,10,15,4,9,14,3,8,13,2,7,12,
    5,8,11,14,1,4,7,10,13,0,3,6,9,12,15,2,
    0,7,14,5,12,3,10,1,8,15,6,13,4,11,2,9 };

// ---- f32 soft ops, exact IEEE-RN, reference association --------------------
__device__ __forceinline__ float fxor(float a, float b) {
    return __fsub_rn(__fadd_rn(a, b), __fmul_rn(__fmul_rn(2.0f, a), b));
}
__device__ __forceinline__ float fand(float a, float b) { return __fmul_rn(a, b); }
__device__ __forceinline__ float forr(float a, float b) {
    return __fsub_rn(__fadd_rn(a, b), __fmul_rn(a, b));
}
__device__ __forceinline__ float fnot(float a) { return __fsub_rn(1.0f, a); }

__device__ __forceinline__ float decst(int st) {
    if (!(st & 1)) return 0.0f;
    return (st & 2) ? __uint_as_float(0x3F7FFFFFu) : 1.0f;
}
__device__ __forceinline__ float fphase(int ph, float b, float c, float d) {
    if (ph == 0) return forr(fand(b, c), fand(fnot(b), d));
    if (ph == 1) return forr(fand(d, b), fand(fnot(d), c));
    if (ph == 2) return fxor(fxor(b, c), d);
    return fxor(c, forr(b, fnot(d)));
}
// deficit predicate: soft_add32 result bit is (1-2^-24) iff hard=1 AND this
__device__ __forceinline__ uint32_t pbit(float x, float y) {
    float px = __fmul_rn(fxor(x, y), 0.5f);
    float r  = __fsub_rn(__fadd_rn(1.0f, px), px);
    return (__float_as_uint(r) != 0x3F800000u) ? 1u : 0u;
}

// ---- RN to 53-bit significand (RNE) of u64, x < 2^57; branchless magic -----
__device__ __forceinline__ uint64_t rn53(uint64_t x) {
    if (x < (1ull << 53)) return x;
    int sh = 11 - __clz((uint32_t)(x >> 32));
    uint64_t m = 1ull << sh;
    uint64_t y = x + (m >> 1) - 1ull + ((x >> sh) & 1ull);
    return y & (0ull - m);
}
// sequential f64 value of a T-valued word, 2^-24 units (R3-validated order)
__device__ __forceinline__ uint64_t tvalm(uint32_t H, uint32_t P) {
    uint64_t E = (((uint64_t)(H & 0x1FFFFFFFu)) << 24) - (uint64_t)(P & 0x1FFFFFFFu);
#pragma unroll
    for (int i = 29; i < 32; i++) {
        uint64_t t = (((uint64_t)((H >> i) & 1u)) << (24 + i)) -
                     (((uint64_t)((P >> i) & 1u)) << i);
        E = rn53(E + t);
    }
    return E;
}
// floor(sv / 2^24) mod 2^32 for nonneg f64 sv < 2^57 — off the CVT pipe
__device__ __forceinline__ uint32_t h32of(double sv) {
    uint64_t b = (uint64_t)__double_as_longlong(sv);
    uint32_t e = (uint32_t)(b >> 52);
    uint64_t m = (b & 0x000FFFFFFFFFFFFFull) | 0x0010000000000000ull;
    uint32_t t = 1099u - e;
    return (t >= 64u) ? 0u : (uint32_t)(m >> t);
}
__device__ __forceinline__ uint32_t spread4(uint32_t x, int q) {
    return (((x >> (4 * q)) & 0xFu) * 0x00204081u) & 0x01010101u;
}
__device__ __forceinline__ uint32_t gatherk(const uint32_t* Y, int k) {
    uint32_t m = 0;
#pragma unroll
    for (int q = 0; q < 8; q++) {
        uint32_t t = (Y[q] >> k) & 0x01010101u;
        m |= (((t * 0x01020408u) >> 24) & 0xFu) << (4 * q);
    }
    return m;
}

// f32 bits (f >= 0) -> f64 bits via integer rebias; exact, zero-safe.
// hi = (v>>3) | 0x38000000 (no carry: v>>3 < 2^27); lo = v<<29.
__device__ __forceinline__ double f32bits2f64(uint32_t v) {
    uint32_t hi = v ? ((v >> 3) | 0x38000000u) : 0u;
    return __hiloint2double((int)hi, (int)(v << 29));
}

// T (+) T soft_add32 on masks (alias-safe)
__device__ __forceinline__ void tadd(uint32_t Hx, uint32_t Px, uint64_t vx,
                                     uint32_t Hy, uint32_t Py, uint64_t vy,
                                     uint32_t& Ho, uint32_t& Po, uint64_t& vo) {
    uint32_t ho = (uint32_t)(rn53(vx + vy) >> 24);
    uint32_t po = ho & (Hx & Hy & (Px | Py));
    uint64_t vv = tvalm(ho, po);
    Ho = ho; Po = po; vo = vv;
}

#define C2P55 36028797018963968.0   // 2^55

// ---- one MD5 compress over byte-packed T-state -------------------------------
template<int BLK2>
__device__ void compress_fn(
    uint32_t& Ha, uint32_t& Pa, uint64_t& va,
    uint32_t& Hb, uint32_t& Pb, uint64_t& vb,
    uint32_t& Hc, uint32_t& Pc, uint64_t& vc,
    uint32_t& Hd, uint32_t& Pd, uint64_t& vd,
    const uint32_t* sTbl,
    const uint64_t* wvu, const uint32_t* m0, const uint32_t* x1, const uint32_t* x2)
{
    // byte-packed state: byte j = b2 | c2<<2 | d2<<4 | a2<<6
    uint32_t Y[8];
#pragma unroll
    for (int q = 0; q < 8; q++) {
        Y[q] = spread4(Hb,q)        | (spread4(Pb,q) << 1)
             | (spread4(Hc,q) << 2) | (spread4(Pc,q) << 3)
             | (spread4(Hd,q) << 4) | (spread4(Pd,q) << 5)
             | (spread4(Ha,q) << 6) | (spread4(Pa,q) << 7);
    }
    uint32_t HB = Hb, PB = Pb;
    double vaf = __ull2double_rn(va), vbf = __ull2double_rn(vb);
    double vcf = __ull2double_rn(vc), vdf = __ull2double_rn(vd);

#pragma unroll 1
    for (int i = 0; i < 64; i++) {
        const uint32_t* ft = sTbl + ((i >> 4) << 8);
        // f-sum: faithful f64 Horner chain; 4B table entries (LDS.32),
        // f64 rebuilt by exact integer rebias (off-chain ALU work)
        double r = 0.0;
        uint32_t pred1 = 0;
#pragma unroll
        for (int q = 0; q < 8; q++) {
            uint32_t yq = Y[q];
            uint32_t t0 = ft[__byte_perm(yq, 0, 0x4440)];
            uint32_t t1 = ft[__byte_perm(yq, 0, 0x4441)];
            uint32_t t2 = ft[__byte_perm(yq, 0, 0x4442)];
            uint32_t t3 = ft[__byte_perm(yq, 0, 0x4443)];
            pred1 |= (t0 >> 31) << (4*q+0);
            r = __fma_rn(r, 0.5, f32bits2f64(t0 & 0x7FFFFFFFu));
            pred1 |= (t1 >> 31) << (4*q+1);
            r = __fma_rn(r, 0.5, f32bits2f64(t1 & 0x7FFFFFFFu));
            pred1 |= (t2 >> 31) << (4*q+2);
            r = __fma_rn(r, 0.5, f32bits2f64(t2 & 0x7FFFFFFFu));
            pred1 |= (t3 >> 31) << (4*q+3);
            r = __fma_rn(r, 0.5, f32bits2f64(t3 & 0x7FFFFFFFu));
        }
        // add1: f-sum + a  (exact product 2^55, one RN == reference)
        double sv = __fma_rn(r, C2P55, vaf);
        uint32_t H1 = h32of(sv);
        uint32_t P1 = H1 & pred1;
        uint64_t v1 = tvalm(H1, P1);
        // add2: + K[i]
        uint32_t Km = cK[i];
        uint32_t H2 = (uint32_t)(rn53(v1 + (((uint64_t)Km) << 24)) >> 24);
        uint32_t P2 = H2 & (Km & P1);
        uint64_t v2 = tvalm(H2, P2);
        // add3: + word[g]
        int g = cG[i];
        uint32_t H3, P3;
        if (BLK2) {
            uint64_t pw  = (g == 0) ? (0x80ull << 24) : ((g == 14) ? (0x200ull << 24) : 0ull);
            uint32_t pwm = (g == 0) ? 0x80u : ((g == 14) ? 0x200u : 0u);
            H3 = (uint32_t)(rn53(v2 + pw) >> 24);
            P3 = H3 & (P2 & pwm);
        } else {
            H3 = (uint32_t)(rn53(v2 + wvu[g]) >> 24);
            uint32_t pr = m0[g] ^ (H2 & x1[g]) ^ (P2 & x2[g]);
            P3 = H3 & pr;
        }
        // rotate, then b = soft_add32(b, rot)
        int sh = cS[i];
        uint32_t H3r = __funnelshift_l(H3, H3, sh);
        uint32_t P3r = __funnelshift_l(P3, P3, sh);
        uint64_t v3 = tvalm(H3r, P3r);
        uint32_t H4 = (uint32_t)(rn53(vb + v3) >> 24);
        uint32_t P4 = H4 & (HB & H3r & (PB | P3r));
        uint64_t v4 = tvalm(H4, P4);
        double v4f = __ull2double_rn(v4);   // exact; consumed next round
        // shift state bytes b->c->d->a; insert new b
#pragma unroll
        for (int q = 0; q < 8; q++) {
            uint32_t bb = spread4(H4, q) | (spread4(P4, q) << 1);
            Y[q] = ((Y[q] & 0x3F3F3F3Fu) << 2) | bb;
        }
        va = vd;  vd = vc;  vc = vb;  vb = v4;
        vaf = vdf; vdf = vcf; vcf = vbf; vbf = v4f;
        HB = H4; PB = P4;
    }
    // recover final masks from Y
    Hb = HB;           Pb = PB;
    Hc = gatherk(Y,2); Pc = gatherk(Y,3);
    Hd = gatherk(Y,4); Pd = gatherk(Y,5);
    Ha = gatherk(Y,6); Pa = gatherk(Y,7);
}

__global__ void __launch_bounds__(TPB)
softmd5_kernel(const float* __restrict__ in, float* __restrict__ out, int B)
{
    // 4 phases x 256 entries: f32(f) bits with pred(code,ast) in the sign bit
    __shared__ uint32_t sTbl[4 * 256];

    int t = threadIdx.x;
    const float ONEME = __uint_as_float(0x3F7FFFFFu);
    for (int k = t; k < 1024; k += TPB) {
        int ph = k >> 8, Bc = k & 255;
        float b = decst(Bc & 3), c = decst((Bc >> 2) & 3), d = decst((Bc >> 4) & 3);
        float a = decst((Bc >> 6) & 3);
        float f = fphase(ph, b, c, d);
        sTbl[k] = __float_as_uint(f) | (pbit(f, a) << 31);   // f >= 0: bit31 free
    }
    __syncthreads();

    int row = blockIdx.x * TPB + t;
    if (row >= B) return;

    const float4* rp = reinterpret_cast<const float4*>(in + (size_t)row * 512);

    // word values: f64 Horner chain (reference-exact), converted to u64 units
    uint64_t wvu[16];
    uint32_t m0[16], x1[16], x2[16];
#pragma unroll 1
    for (int g = 0; g < 16; g++) {
        double hr = 0.0;
        uint32_t a0 = 0, a1 = 0, a2 = 0;
        for (int q = 0; q < 8; q++) {
            float4 w4 = rp[g * 8 + q];
            float w[4] = { w4.x, w4.y, w4.z, w4.w };
#pragma unroll
            for (int u = 0; u < 4; u++) {
                int j = q * 4 + u;
                hr = __fma_rn(hr, 0.5, (double)w[u]);
                a0 |= pbit(0.0f,  w[u]) << j;
                a1 |= pbit(1.0f,  w[u]) << j;
                a2 |= pbit(ONEME, w[u]) << j;
            }
        }
        wvu[g] = __double2ull_rz(__dmul_rn(hr, C2P55));
        m0[g] = a0; x1[g] = a0 ^ a1; x2[g] = a1 ^ a2;
    }

    // H-state (T-masks + cached value, 2^-24 units u64)
    uint32_t HA = 0x67452301u, PA = 0, HB = 0xefcdab89u, PB = 0;
    uint32_t HC = 0x98badcfeu, PC = 0, HD = 0x10325476u, PD = 0;
    uint64_t VA = ((uint64_t)HA) << 24, VB = ((uint64_t)HB) << 24;
    uint64_t VC = ((uint64_t)HC) << 24, VD = ((uint64_t)HD) << 24;

    // ---- block 1 ----
    {
        uint32_t ha=HA,pa=PA,hb=HB,pb=PB,hc=HC,pc=PC,hd=HD,pd=PD;
        uint64_t va=VA,vb=VB,vc=VC,vd=VD;
        compress_fn<0>(ha,pa,va, hb,pb,vb, hc,pc,vc, hd,pd,vd,
                       sTbl, wvu, m0, x1, x2);
        tadd(HA,PA,VA, ha,pa,va, HA,PA,VA);
        tadd(HB,PB,VB, hb,pb,vb, HB,PB,VB);
        tadd(HC,PC,VC, hc,pc,vc, HC,PC,VC);
        tadd(HD,PD,VD, hd,pd,vd, HD,PD,VD);
    }
    // ---- block 2 (constant padding) ----
    {
        uint32_t ha=HA,pa=PA,hb=HB,pb=PB,hc=HC,pc=PC,hd=HD,pd=PD;
        uint64_t va=VA,vb=VB,vc=VC,vd=VD;
        compress_fn<1>(ha,pa,va, hb,pb,vb, hc,pc,vc, hd,pd,vd,
                       sTbl, wvu, m0, x1, x2);
        tadd(HA,PA,VA, ha,pa,va, HA,PA,VA);
        tadd(HB,PB,VB, hb,pb,vb, HB,PB,VB);
        tadd(HC,PC,VC, hc,pc,vc, HC,PC,VC);
        tadd(HD,PD,VD, hd,pd,vd, HD,PD,VD);
    }

    // ---- emit 128 float bits ----
    float4* op = reinterpret_cast<float4*>(out + (size_t)row * 128);
    uint32_t Hs[4] = { HA, HB, HC, HD }, Ps[4] = { PA, PB, PC, PD };
#pragma unroll
    for (int w = 0; w < 4; w++) {
        uint32_t Hm = Hs[w], Pm = Ps[w];
#pragma unroll
        for (int j = 0; j < 32; j += 4) {
            float4 f4;
            f4.x = __uint_as_float(((Hm>>(j+0))&1u) ? (((Pm>>(j+0))&1u)?0x3F7FFFFFu:0x3F800000u) : 0u);
            f4.y = __uint_as_float(((Hm>>(j+1))&1u) ? (((Pm>>(j+1))&1u)?0x3F7FFFFFu:0x3F800000u) : 0u);
            f4.z = __uint_as_float(((Hm>>(j+2))&1u) ? (((Pm>>(j+2))&1u)?0x3F7FFFFFu:0x3F800000u) : 0u);
            f4.w = __uint_as_float(((Hm>>(j+3))&1u) ? (((Pm>>(j+3))&1u)?0x3F7FFFFFu:0x3F800000u) : 0u);
            op[w*8 + (j>>2)] = f4;
        }
    }
}

extern "C" void kernel_launch(void* const* d_in, const int* in_sizes, int n_in,
                              void* d_out, int out_size)
{
    const float* in = (const float*)d_in[0];
    float* out = (float*)d_out;
    int B = in_sizes[0] / 512;            // 131072 rows
    int blocks = (B + TPB - 1) / TPB;
    softmd5_kernel<<<blocks, TPB>>>(in, out, B);
}